// round 4
// baseline (speedup 1.0000x reference)
#include <cuda_runtime.h>
#include <cstdint>

// ExpandMask: x [B=64, 1, L=262144] f32  ->  out [B, 1, 2L] float (0.0/1.0)
//   out[2i]   = (x[i-1] + x[i] + x[i+1] > 0.5) ? 1 : 0   (zero taps outside row)
//   out[2i+1] = (x[i]   + x[i+1]        > 0.5) ? 1 : 0
//
// R4: 16 inputs / 32 outputs per thread. 4 independent front-batched LDG.128
// (MLP=4) + 8 STG.128. Halos via warp shuffle; lane-edge halos via 4B loads.

static constexpr int L = 262144;               // input row length
static constexpr int ELEMS_PER_THREAD = 16;    // inputs per thread
static constexpr int THREADS_PER_ROW = L / ELEMS_PER_THREAD;  // 16384

__global__ void __launch_bounds__(256) expand_mask_kernel(
    const float* __restrict__ x, float4* __restrict__ out)
{
    const int tid  = blockIdx.x * blockDim.x + threadIdx.x;
    const int row  = tid / THREADS_PER_ROW;
    const int tr   = tid - row * THREADS_PER_ROW;   // thread index within row
    const int lane = threadIdx.x & 31;

    const int ibase = row * L + tr * ELEMS_PER_THREAD;

    // Front-batched independent 128-bit loads (MLP = 4)
    const float4 v0 = __ldcs(reinterpret_cast<const float4*>(x + ibase));
    const float4 v1 = __ldcs(reinterpret_cast<const float4*>(x + ibase + 4));
    const float4 v2 = __ldcs(reinterpret_cast<const float4*>(x + ibase + 8));
    const float4 v3 = __ldcs(reinterpret_cast<const float4*>(x + ibase + 12));

    float a[18];
    a[1]  = v0.x; a[2]  = v0.y; a[3]  = v0.z; a[4]  = v0.w;
    a[5]  = v1.x; a[6]  = v1.y; a[7]  = v1.z; a[8]  = v1.w;
    a[9]  = v2.x; a[10] = v2.y; a[11] = v2.z; a[12] = v2.w;
    a[13] = v3.x; a[14] = v3.y; a[15] = v3.z; a[16] = v3.w;

    // Halos from neighboring lanes (warp covers 512 contiguous floats;
    // warps never straddle rows since THREADS_PER_ROW = 16384 is warp-aligned).
    float left  = __shfl_up_sync(0xffffffffu, a[16], 1);
    float right = __shfl_down_sync(0xffffffffu, a[1], 1);
    if (lane == 0)
        left  = (tr == 0) ? 0.0f : __ldg(x + ibase - 1);
    if (lane == 31)
        right = (tr == THREADS_PER_ROW - 1) ? 0.0f : __ldg(x + ibase + ELEMS_PER_THREAD);
    a[0]  = left;
    a[17] = right;

    // 32 output floats: for local input j (0..15):
    //   o[2j]   = (a[j] + a[j+1] + a[j+2] > 0.5)
    //   o[2j+1] = (a[j+1] + a[j+2]        > 0.5)
    const long ovec = ((long)row * 2 * L + (long)tr * 2 * ELEMS_PER_THREAD) / 4;

    #pragma unroll
    for (int q = 0; q < 8; q++) {
        const int j = 2 * q;          // float4 q covers inputs j, j+1
        const float ps0 = a[j + 1] + a[j + 2];
        const float ps1 = a[j + 2] + a[j + 3];
        float4 o;
        o.x = (a[j]     + ps0) > 0.5f ? 1.0f : 0.0f;
        o.y =              ps0  > 0.5f ? 1.0f : 0.0f;
        o.z = (a[j + 1] + ps1) > 0.5f ? 1.0f : 0.0f;
        o.w =              ps1  > 0.5f ? 1.0f : 0.0f;
        __stcs(&out[ovec + q], o);
    }
}

extern "C" void kernel_launch(void* const* d_in, const int* in_sizes, int n_in,
                              void* d_out, int out_size)
{
    const float* x = (const float*)d_in[0];
    float4* out = (float4*)d_out;

    const int n_in_elems = in_sizes[0];                 // 64 * 262144
    const int total_threads = n_in_elems / ELEMS_PER_THREAD;
    const int block = 256;
    const int grid = (total_threads + block - 1) / block;

    expand_mask_kernel<<<grid, block>>>(x, out);
}

// round 5
// speedup vs baseline: 1.5425x; 1.5425x over previous
#include <cuda_runtime.h>
#include <cstdint>

// ExpandMask: x [B=64, 1, L=262144] f32 -> out [B, 1, 2L] float (0.0/1.0)
//   out[2i]   = (x[i-1] + x[i] + x[i+1] > 0.5)   (zero taps outside row)
//   out[2i+1] = (x[i]   + x[i+1]        > 0.5)
//
// R5: fully coalesced mapping. Each thread handles ONE output float4 per
// chunk: out float4 index o -> needs input float2 index o plus halo taps.
// Consecutive lanes own consecutive o -> dense LDG.64 loads and dense
// STG.128 stores (minimal L1 wavefronts). Halos via warp shuffle; lane 0/31
// edges via predicated scalar loads. 4 block-strided chunks/thread (MLP=4).

static constexpr int L = 262144;                    // input row length
static constexpr int OUT_F4_PER_ROW = (2 * L) / 4;  // 131072 = 2^17
static constexpr int CHUNKS = 4;
static constexpr int BLOCK = 256;

__global__ void __launch_bounds__(BLOCK) expand_mask_kernel(
    const float* __restrict__ x, float4* __restrict__ out)
{
    const int lane = threadIdx.x & 31;
    const int block_base = blockIdx.x * (BLOCK * CHUNKS);

    // Front-batch the 4 independent dense float2 loads (MLP = 4).
    int o[CHUNKS], ibase[CHUNKS], p[CHUNKS];
    float2 e[CHUNKS];
    #pragma unroll
    for (int c = 0; c < CHUNKS; c++) {
        o[c] = block_base + c * BLOCK + threadIdx.x;     // output float4 idx
        const int r = o[c] >> 17;                        // row (OUT_F4_PER_ROW = 2^17)
        p[c] = o[c] & (OUT_F4_PER_ROW - 1);              // position within row
        ibase[c] = r * L + 2 * p[c];                     // input float index
        e[c] = __ldcs(reinterpret_cast<const float2*>(x + ibase[c]));
    }

    #pragma unroll
    for (int c = 0; c < CHUNKS; c++) {
        // Halo taps: left = x[2p-1], right = x[2p+2] (zero outside row).
        float left  = __shfl_up_sync(0xffffffffu, e[c].y, 1);
        float right = __shfl_down_sync(0xffffffffu, e[c].x, 1);
        if (lane == 0)
            left  = (p[c] == 0) ? 0.0f : __ldg(x + ibase[c] - 1);
        if (lane == 31)
            right = (p[c] == OUT_F4_PER_ROW - 1) ? 0.0f : __ldg(x + ibase[c] + 2);

        const float s01 = e[c].x + e[c].y;   // x[2p] + x[2p+1]
        float4 ov;
        ov.x = (left + s01)  > 0.5f ? 1.0f : 0.0f;   // out[4p]
        ov.y =  s01          > 0.5f ? 1.0f : 0.0f;   // out[4p+1]
        ov.z = (s01 + right) > 0.5f ? 1.0f : 0.0f;   // out[4p+2]
        ov.w = (e[c].y + right) > 0.5f ? 1.0f : 0.0f; // out[4p+3]

        __stcs(&out[o[c]], ov);
    }
}

extern "C" void kernel_launch(void* const* d_in, const int* in_sizes, int n_in,
                              void* d_out, int out_size)
{
    const float* x = (const float*)d_in[0];
    float4* out = (float4*)d_out;

    const int total_out_f4 = (2 * in_sizes[0]) / 4;      // 8388608
    const int grid = total_out_f4 / (BLOCK * CHUNKS);    // 8192

    expand_mask_kernel<<<grid, BLOCK>>>(x, out);
}